// round 11
// baseline (speedup 1.0000x reference)
#include <cuda_runtime.h>
#include <cuda_fp16.h>
#include <math.h>
#include <stdint.h>

typedef unsigned long long ull;

// ---------------- problem constants ----------------
#define HID  2048
#define R4   8192          // 4 * HID
#define TLEN 4096
#define IDIM 1024

// ---------------- recurrence kernel config ----------------
#define NBLK   128
#define NTHR   512
#define HPB    16          // h indices per block (2048 / 128)
#define NCACHE 48          // rows of W_hh (fp16) cached in SMEM per block (gates i,f,g)

// smem: 48 rows * 2048 halfs + h 2048 halfs
#define REC_SMEM_BYTES (NCACHE * HID * 2 + HID * 2)

// ---------------- scratch (device globals; no allocation) ----------------
__device__ float    g_xg[(size_t)TLEN * R4];      // precomputed input gates, 128 MB
__device__ __half   g_whh[(size_t)R4 * HID];      // fp16 copy of W_hh, 32 MB

// message line: 16 h values (fp32) + tag, one 128B line per block, double buffered
struct alignas(128) Msg { float h[16]; unsigned tag; unsigned pad[15]; };
__device__ Msg g_msg[2][NBLK];

// ---------------- acquire helper ----------------
__device__ __forceinline__ unsigned ld_acq_(const unsigned* p) {
    unsigned v;
    asm volatile("ld.global.acquire.gpu.b32 %0, [%1];" : "=r"(v) : "l"(p) : "memory");
    return v;
}

// ---------------- init ----------------
__global__ void init_kernel() {
    unsigned* p = reinterpret_cast<unsigned*>(g_msg);
    for (int i = threadIdx.x; i < 2 * NBLK * 32; i += blockDim.x) p[i] = 0u;
}

// ---------------- W_hh fp32 -> fp16 ----------------
__global__ void prep_whh(const float* __restrict__ W_hh) {
    const size_t n2 = (size_t)R4 * HID / 2;
    const size_t stride = (size_t)gridDim.x * blockDim.x;
    for (size_t i = (size_t)blockIdx.x * blockDim.x + threadIdx.x; i < n2; i += stride) {
        float2 v = reinterpret_cast<const float2*>(W_hh)[i];
        reinterpret_cast<__half2*>(g_whh)[i] = __floats2half2_rn(v.x, v.y);
    }
}

// ---------------- xg GEMM: 128x128x16 tiles, 8x8 micro (proven) ----------------
#define GBM 128
#define GBN 128
#define GBK 16
#define GAP 132

__global__ __launch_bounds__(256) void xg_gemm(const float* __restrict__ x,
                                               const float* __restrict__ W_ih,
                                               const float* __restrict__ b_ih,
                                               const float* __restrict__ b_hh) {
    __shared__ float As[GBK * GAP];
    __shared__ float Bs[GBK * GAP];
    const int tid = threadIdx.x;
    const int tx = tid & 15;
    const int ty = tid >> 4;
    const int rt = blockIdx.x * GBN;
    const int tt = blockIdx.y * GBM;

    const int lr = tid >> 2;
    const int lc = (tid & 3) * 4;

    float acc[2][2][4][4];
    #pragma unroll
    for (int a = 0; a < 2; a++)
        #pragma unroll
        for (int b = 0; b < 2; b++)
            #pragma unroll
            for (int i = 0; i < 4; i++)
                #pragma unroll
                for (int j = 0; j < 4; j++) acc[a][b][i][j] = 0.f;

    for (int k0 = 0; k0 < IDIM; k0 += GBK) {
        float4 a0 = __ldg(reinterpret_cast<const float4*>(&x[(size_t)(tt + lr) * IDIM + k0 + lc]));
        float4 a1 = __ldg(reinterpret_cast<const float4*>(&x[(size_t)(tt + lr + 64) * IDIM + k0 + lc]));
        float4 w0 = __ldg(reinterpret_cast<const float4*>(&W_ih[(size_t)(rt + lr) * IDIM + k0 + lc]));
        float4 w1 = __ldg(reinterpret_cast<const float4*>(&W_ih[(size_t)(rt + lr + 64) * IDIM + k0 + lc]));

        As[(lc + 0) * GAP + lr] = a0.x; As[(lc + 1) * GAP + lr] = a0.y;
        As[(lc + 2) * GAP + lr] = a0.z; As[(lc + 3) * GAP + lr] = a0.w;
        As[(lc + 0) * GAP + lr + 64] = a1.x; As[(lc + 1) * GAP + lr + 64] = a1.y;
        As[(lc + 2) * GAP + lr + 64] = a1.z; As[(lc + 3) * GAP + lr + 64] = a1.w;

        Bs[(lc + 0) * GAP + lr] = w0.x; Bs[(lc + 1) * GAP + lr] = w0.y;
        Bs[(lc + 2) * GAP + lr] = w0.z; Bs[(lc + 3) * GAP + lr] = w0.w;
        Bs[(lc + 0) * GAP + lr + 64] = w1.x; Bs[(lc + 1) * GAP + lr + 64] = w1.y;
        Bs[(lc + 2) * GAP + lr + 64] = w1.z; Bs[(lc + 3) * GAP + lr + 64] = w1.w;

        __syncthreads();

        #pragma unroll
        for (int k = 0; k < GBK; k++) {
            float4 av0 = *reinterpret_cast<const float4*>(&As[k * GAP + ty * 4]);
            float4 av1 = *reinterpret_cast<const float4*>(&As[k * GAP + 64 + ty * 4]);
            float4 bv0 = *reinterpret_cast<const float4*>(&Bs[k * GAP + tx * 4]);
            float4 bv1 = *reinterpret_cast<const float4*>(&Bs[k * GAP + 64 + tx * 4]);
            float am[2][4] = {{av0.x, av0.y, av0.z, av0.w}, {av1.x, av1.y, av1.z, av1.w}};
            float bn[2][4] = {{bv0.x, bv0.y, bv0.z, bv0.w}, {bv1.x, bv1.y, bv1.z, bv1.w}};
            #pragma unroll
            for (int a = 0; a < 2; a++)
                #pragma unroll
                for (int i = 0; i < 4; i++)
                    #pragma unroll
                    for (int b = 0; b < 2; b++)
                        #pragma unroll
                        for (int j = 0; j < 4; j++)
                            acc[a][b][i][j] += am[a][i] * bn[b][j];
        }
        __syncthreads();
    }

    #pragma unroll
    for (int b = 0; b < 2; b++) {
        const int rbase = rt + b * 64 + tx * 4;
        float bias[4];
        #pragma unroll
        for (int j = 0; j < 4; j++) bias[j] = b_ih[rbase + j] + b_hh[rbase + j];
        #pragma unroll
        for (int a = 0; a < 2; a++) {
            #pragma unroll
            for (int i = 0; i < 4; i++) {
                const int t = tt + a * 64 + ty * 4 + i;
                float4 o;
                o.x = acc[a][b][i][0] + bias[0];
                o.y = acc[a][b][i][1] + bias[1];
                o.z = acc[a][b][i][2] + bias[2];
                o.w = acc[a][b][i][3] + bias[3];
                *reinterpret_cast<float4*>(&g_xg[(size_t)t * R4 + rbase]) = o;
            }
        }
    }
}

// fast sigmoid/tanh via HW EX2 path
__device__ __forceinline__ float sigmoidf_(float v) { return 1.0f / (1.0f + __expf(-v)); }
__device__ __forceinline__ float tanhf_(float v)    { return 2.0f / (1.0f + __expf(-2.0f * v)) - 1.0f; }
__device__ __forceinline__ __half2 u2h_(unsigned u) { return *reinterpret_cast<__half2*>(&u); }

// ---------------- persistent LSTM recurrence ----------------
// Warp w owns h index (hbase + w): computes its 4 gate rows.
// Gates i,f,g from SMEM (rows w, 16+w, 32+w); gate o register-resident.
// After warp reduce, lane 0 holds all 4 gates -> activation + c (register) + publish.
__global__ __launch_bounds__(NTHR, 1) void lstm_rec() {
    extern __shared__ float smem[];
    __half* wc    = reinterpret_cast<__half*>(smem);         // NCACHE * HID halfs
    __half* h2_sh = wc + NCACHE * HID;                       // HID halfs

    const int tid   = threadIdx.x;
    const int bid   = blockIdx.x;
    const int hbase = bid * HPB;
    const int warp  = tid >> 5;
    const int lane  = tid & 31;

    // stage local rows 0..47 (gates i,f,g) into SMEM as fp16 (once)
    for (int idx = tid; idx < NCACHE * HID / 8; idx += NTHR) {
        const int lr  = idx >> 8;
        const int col = (idx & 255) * 8;
        const int gate = lr >> 4;
        const int hl   = lr & 15;
        const size_t row = (size_t)(gate * HID + hbase + hl);
        reinterpret_cast<uint4*>(wc + (size_t)lr * HID)[col / 8] =
            __ldg(reinterpret_cast<const uint4*>(g_whh + row * HID + col));
    }

    // o-gate row for this warp's h index: register-resident (8 x uint4 = 32 regs)
    uint4 wreg[8];
    {
        const __half* wo = g_whh + (size_t)(3 * HID + hbase + warp) * HID;
        #pragma unroll
        for (int ch = 0; ch < 8; ch++)
            wreg[ch] = __ldg(reinterpret_cast<const uint4*>(wo + ch * 256 + lane * 8));
    }

    // this warp's smem rows (gates i, f, g for h index hbase+warp)
    const __half* ws0 = wc + (size_t)(warp) * HID;
    const __half* ws1 = wc + (size_t)(16 + warp) * HID;
    const __half* ws2 = wc + (size_t)(32 + warp) * HID;

    // xg element for lanes 0..3: gate = lane, row = lane*HID + hbase + warp
    const size_t my_xg_row = (size_t)lane * HID + (size_t)(hbase + warp);

    // cell state for this warp's h index (live in lane 0's register)
    float c_reg = 0.0f;

    // message staging: thread stages 4 floats of line (tid>>2)
    const int mb = tid >> 2;
    const int mq = tid & 3;

    for (int t = 0; t < TLEN; t++) {
        // xg prefetch (h-independent, overlaps the wait)
        float xgl = 0.f;
        if (lane < 4)
            xgl = __ldg(g_xg + (size_t)t * R4 + my_xg_row);

        // poll-and-stage: acquire-load tag, then pull h quarter
        {
            const Msg* ml = &g_msg[t & 1][mb];
            while (ld_acq_(&ml->tag) < (unsigned)t) { }
            float4 v = __ldcg(reinterpret_cast<const float4*>(ml->h + mq * 4));
            __half2 p0 = __floats2half2_rn(v.x, v.y);
            __half2 p1 = __floats2half2_rn(v.z, v.w);
            uint2 u;
            u.x = *reinterpret_cast<unsigned*>(&p0);
            u.y = *reinterpret_cast<unsigned*>(&p1);
            reinterpret_cast<uint2*>(h2_sh)[tid] = u;
        }
        __syncthreads();                                    // h2_sh complete

        // 3 smem rows + 1 reg row dot, HFMA2 chunks -> f32x2 accumulators
        ull acc0 = 0ull, acc1 = 0ull, acc2 = 0ull, acc3 = 0ull;
        #pragma unroll
        for (int ch = 0; ch < 8; ch++) {
            const int off = ch * 256 + lane * 8;   // half index
            uint4 hv = *reinterpret_cast<const uint4*>(h2_sh + off);
            uint4 w0 = *reinterpret_cast<const uint4*>(ws0 + off);
            uint4 w1 = *reinterpret_cast<const uint4*>(ws1 + off);
            uint4 w2 = *reinterpret_cast<const uint4*>(ws2 + off);
            uint4 w3 = wreg[ch];

            __half2 s0 = __hmul2(u2h_(w0.x), u2h_(hv.x));
            s0 = __hfma2(u2h_(w0.y), u2h_(hv.y), s0);
            s0 = __hfma2(u2h_(w0.z), u2h_(hv.z), s0);
            s0 = __hfma2(u2h_(w0.w), u2h_(hv.w), s0);
            __half2 s1 = __hmul2(u2h_(w1.x), u2h_(hv.x));
            s1 = __hfma2(u2h_(w1.y), u2h_(hv.y), s1);
            s1 = __hfma2(u2h_(w1.z), u2h_(hv.z), s1);
            s1 = __hfma2(u2h_(w1.w), u2h_(hv.w), s1);
            __half2 s2 = __hmul2(u2h_(w2.x), u2h_(hv.x));
            s2 = __hfma2(u2h_(w2.y), u2h_(hv.y), s2);
            s2 = __hfma2(u2h_(w2.z), u2h_(hv.z), s2);
            s2 = __hfma2(u2h_(w2.w), u2h_(hv.w), s2);
            __half2 s3 = __hmul2(u2h_(w3.x), u2h_(hv.x));
            s3 = __hfma2(u2h_(w3.y), u2h_(hv.y), s3);
            s3 = __hfma2(u2h_(w3.z), u2h_(hv.z), s3);
            s3 = __hfma2(u2h_(w3.w), u2h_(hv.w), s3);

            float2 f0 = __half22float2(s0);
            float2 f1 = __half22float2(s1);
            float2 f2 = __half22float2(s2);
            float2 f3 = __half22float2(s3);
            ull ff;
            asm("mov.b64 %0, {%1, %2};" : "=l"(ff) : "f"(f0.x), "f"(f0.y));
            asm("add.rn.f32x2 %0, %0, %1;" : "+l"(acc0) : "l"(ff));
            asm("mov.b64 %0, {%1, %2};" : "=l"(ff) : "f"(f1.x), "f"(f1.y));
            asm("add.rn.f32x2 %0, %0, %1;" : "+l"(acc1) : "l"(ff));
            asm("mov.b64 %0, {%1, %2};" : "=l"(ff) : "f"(f2.x), "f"(f2.y));
            asm("add.rn.f32x2 %0, %0, %1;" : "+l"(acc2) : "l"(ff));
            asm("mov.b64 %0, {%1, %2};" : "=l"(ff) : "f"(f3.x), "f"(f3.y));
            asm("add.rn.f32x2 %0, %0, %1;" : "+l"(acc3) : "l"(ff));
        }

        float a0, a1, a2, a3;
        {
            float lo, hi;
            asm("mov.b64 {%0, %1}, %2;" : "=f"(lo), "=f"(hi) : "l"(acc0)); a0 = lo + hi;
            asm("mov.b64 {%0, %1}, %2;" : "=f"(lo), "=f"(hi) : "l"(acc1)); a1 = lo + hi;
            asm("mov.b64 {%0, %1}, %2;" : "=f"(lo), "=f"(hi) : "l"(acc2)); a2 = lo + hi;
            asm("mov.b64 {%0, %1}, %2;" : "=f"(lo), "=f"(hi) : "l"(acc3)); a3 = lo + hi;
        }
        #pragma unroll
        for (int off = 16; off; off >>= 1) {
            a0 += __shfl_xor_sync(0xFFFFFFFFu, a0, off);
            a1 += __shfl_xor_sync(0xFFFFFFFFu, a1, off);
            a2 += __shfl_xor_sync(0xFFFFFFFFu, a2, off);
            a3 += __shfl_xor_sync(0xFFFFFFFFu, a3, off);
        }
        // gather lane-held xg values to lane 0
        const float x0 = __shfl_sync(0xFFFFFFFFu, xgl, 0);
        const float x1 = __shfl_sync(0xFFFFFFFFu, xgl, 1);
        const float x2 = __shfl_sync(0xFFFFFFFFu, xgl, 2);
        const float x3 = __shfl_sync(0xFFFFFFFFu, xgl, 3);

        // lane 0: full LSTM cell update for h index (hbase + warp), publish h
        if (lane == 0) {
            const float iv = sigmoidf_(a0 + x0);
            const float fv = sigmoidf_(a1 + x1);
            const float gv = tanhf_(a2 + x2);
            const float ov = sigmoidf_(a3 + x3);
            c_reg = fv * c_reg + iv * gv;
            g_msg[(t + 1) & 1][bid].h[warp] = ov * tanhf_(c_reg);
        }
        __syncthreads();                                    // all 16 h stores done
        if (tid == 0) {
            __threadfence();                                // cumulative: order h stores
            *(volatile unsigned*)&g_msg[(t + 1) & 1][bid].tag = (unsigned)(t + 1);
        }
    }
}

// ---------------- output layer ----------------
__global__ void out_kernel(const float* __restrict__ W_out,
                           const float* __restrict__ b_out,
                           float* __restrict__ out) {
    __shared__ float red[8];
    const int tid = threadIdx.x;   // 256 threads
    float s = 0.f;
    for (int j = tid; j < HID; j += 256) {
        float hv = g_msg[0][j >> 4].h[j & 15];   // final h (TLEN even -> buffer 0)
        s += hv * W_out[j];
    }
    #pragma unroll
    for (int off = 16; off; off >>= 1) s += __shfl_xor_sync(0xFFFFFFFFu, s, off);
    if ((tid & 31) == 0) red[tid >> 5] = s;
    __syncthreads();
    if (tid < 8) {
        float v = red[tid];
        #pragma unroll
        for (int off = 4; off; off >>= 1) v += __shfl_xor_sync(0xFFu, v, off);
        if (tid == 0) out[0] = v + b_out[0];
    }
}

// ---------------- launch ----------------
extern "C" void kernel_launch(void* const* d_in, const int* in_sizes, int n_in,
                              void* d_out, int out_size) {
    const float* x     = (const float*)d_in[0];
    const float* W_ih  = (const float*)d_in[1];
    const float* W_hh  = (const float*)d_in[2];
    const float* b_ih  = (const float*)d_in[3];
    const float* b_hh  = (const float*)d_in[4];
    const float* W_out = (const float*)d_in[5];
    const float* b_out = (const float*)d_in[6];
    float* out = (float*)d_out;

    init_kernel<<<1, 256>>>();
    prep_whh<<<2048, 256>>>(W_hh);

    dim3 ggrid(R4 / GBN, TLEN / GBM);
    xg_gemm<<<ggrid, 256>>>(x, W_ih, b_ih, b_hh);

    cudaFuncSetAttribute(lstm_rec, cudaFuncAttributeMaxDynamicSharedMemorySize, REC_SMEM_BYTES);
    lstm_rec<<<NBLK, NTHR, REC_SMEM_BYTES>>>();

    out_kernel<<<1, 256>>>(W_out, b_out, out);
}

// round 13
// speedup vs baseline: 1.4118x; 1.4118x over previous
#include <cuda_runtime.h>
#include <cuda_fp16.h>
#include <math.h>
#include <stdint.h>

typedef unsigned long long ull;

// ---------------- problem constants ----------------
#define HID  2048
#define R4   8192          // 4 * HID
#define TLEN 4096
#define IDIM 1024

// ---------------- recurrence kernel config ----------------
#define NBLK   128
#define NTHR   512
#define HPB    16          // h indices per block (2048 / 128)
#define NCACHE 48          // rows of W_hh (fp16) cached in SMEM per block (gates i,f,g)

// smem: 48 rows * 2048 halfs + h 2048 halfs + g 64 f + c 16 f
#define REC_SMEM_BYTES (NCACHE * HID * 2 + HID * 2 + (64 + 16) * 4)

// ---------------- scratch (device globals; no allocation) ----------------
__device__ float    g_xg[(size_t)TLEN * R4];      // precomputed input gates, 128 MB
__device__ __half   g_whh[(size_t)R4 * HID];      // fp16 copy of W_hh, 32 MB

// message line: 16 h values (fp32) + tag, one 128B line per block, double buffered
struct alignas(128) Msg { float h[16]; unsigned tag; unsigned pad[15]; };
__device__ Msg g_msg[2][NBLK];

// ---------------- acquire / release helpers ----------------
__device__ __forceinline__ unsigned ld_acq_(const unsigned* p) {
    unsigned v;
    asm volatile("ld.global.acquire.gpu.b32 %0, [%1];" : "=r"(v) : "l"(p) : "memory");
    return v;
}
__device__ __forceinline__ void st_rel_(unsigned* p, unsigned v) {
    asm volatile("st.global.release.gpu.b32 [%0], %1;" :: "l"(p), "r"(v) : "memory");
}

// ---------------- init ----------------
__global__ void init_kernel() {
    unsigned* p = reinterpret_cast<unsigned*>(g_msg);
    for (int i = threadIdx.x; i < 2 * NBLK * 32; i += blockDim.x) p[i] = 0u;
}

// ---------------- W_hh fp32 -> fp16 ----------------
__global__ void prep_whh(const float* __restrict__ W_hh) {
    const size_t n2 = (size_t)R4 * HID / 2;
    const size_t stride = (size_t)gridDim.x * blockDim.x;
    for (size_t i = (size_t)blockIdx.x * blockDim.x + threadIdx.x; i < n2; i += stride) {
        float2 v = reinterpret_cast<const float2*>(W_hh)[i];
        reinterpret_cast<__half2*>(g_whh)[i] = __floats2half2_rn(v.x, v.y);
    }
}

// ---------------- xg GEMM: 128x128x16 tiles, 8x8 micro (proven) ----------------
#define GBM 128
#define GBN 128
#define GBK 16
#define GAP 132

__global__ __launch_bounds__(256) void xg_gemm(const float* __restrict__ x,
                                               const float* __restrict__ W_ih,
                                               const float* __restrict__ b_ih,
                                               const float* __restrict__ b_hh) {
    __shared__ float As[GBK * GAP];
    __shared__ float Bs[GBK * GAP];
    const int tid = threadIdx.x;
    const int tx = tid & 15;
    const int ty = tid >> 4;
    const int rt = blockIdx.x * GBN;
    const int tt = blockIdx.y * GBM;

    const int lr = tid >> 2;
    const int lc = (tid & 3) * 4;

    float acc[2][2][4][4];
    #pragma unroll
    for (int a = 0; a < 2; a++)
        #pragma unroll
        for (int b = 0; b < 2; b++)
            #pragma unroll
            for (int i = 0; i < 4; i++)
                #pragma unroll
                for (int j = 0; j < 4; j++) acc[a][b][i][j] = 0.f;

    for (int k0 = 0; k0 < IDIM; k0 += GBK) {
        float4 a0 = __ldg(reinterpret_cast<const float4*>(&x[(size_t)(tt + lr) * IDIM + k0 + lc]));
        float4 a1 = __ldg(reinterpret_cast<const float4*>(&x[(size_t)(tt + lr + 64) * IDIM + k0 + lc]));
        float4 w0 = __ldg(reinterpret_cast<const float4*>(&W_ih[(size_t)(rt + lr) * IDIM + k0 + lc]));
        float4 w1 = __ldg(reinterpret_cast<const float4*>(&W_ih[(size_t)(rt + lr + 64) * IDIM + k0 + lc]));

        As[(lc + 0) * GAP + lr] = a0.x; As[(lc + 1) * GAP + lr] = a0.y;
        As[(lc + 2) * GAP + lr] = a0.z; As[(lc + 3) * GAP + lr] = a0.w;
        As[(lc + 0) * GAP + lr + 64] = a1.x; As[(lc + 1) * GAP + lr + 64] = a1.y;
        As[(lc + 2) * GAP + lr + 64] = a1.z; As[(lc + 3) * GAP + lr + 64] = a1.w;

        Bs[(lc + 0) * GAP + lr] = w0.x; Bs[(lc + 1) * GAP + lr] = w0.y;
        Bs[(lc + 2) * GAP + lr] = w0.z; Bs[(lc + 3) * GAP + lr] = w0.w;
        Bs[(lc + 0) * GAP + lr + 64] = w1.x; Bs[(lc + 1) * GAP + lr + 64] = w1.y;
        Bs[(lc + 2) * GAP + lr + 64] = w1.z; Bs[(lc + 3) * GAP + lr + 64] = w1.w;

        __syncthreads();

        #pragma unroll
        for (int k = 0; k < GBK; k++) {
            float4 av0 = *reinterpret_cast<const float4*>(&As[k * GAP + ty * 4]);
            float4 av1 = *reinterpret_cast<const float4*>(&As[k * GAP + 64 + ty * 4]);
            float4 bv0 = *reinterpret_cast<const float4*>(&Bs[k * GAP + tx * 4]);
            float4 bv1 = *reinterpret_cast<const float4*>(&Bs[k * GAP + 64 + tx * 4]);
            float am[2][4] = {{av0.x, av0.y, av0.z, av0.w}, {av1.x, av1.y, av1.z, av1.w}};
            float bn[2][4] = {{bv0.x, bv0.y, bv0.z, bv0.w}, {bv1.x, bv1.y, bv1.z, bv1.w}};
            #pragma unroll
            for (int a = 0; a < 2; a++)
                #pragma unroll
                for (int i = 0; i < 4; i++)
                    #pragma unroll
                    for (int b = 0; b < 2; b++)
                        #pragma unroll
                        for (int j = 0; j < 4; j++)
                            acc[a][b][i][j] += am[a][i] * bn[b][j];
        }
        __syncthreads();
    }

    #pragma unroll
    for (int b = 0; b < 2; b++) {
        const int rbase = rt + b * 64 + tx * 4;
        float bias[4];
        #pragma unroll
        for (int j = 0; j < 4; j++) bias[j] = b_ih[rbase + j] + b_hh[rbase + j];
        #pragma unroll
        for (int a = 0; a < 2; a++) {
            #pragma unroll
            for (int i = 0; i < 4; i++) {
                const int t = tt + a * 64 + ty * 4 + i;
                float4 o;
                o.x = acc[a][b][i][0] + bias[0];
                o.y = acc[a][b][i][1] + bias[1];
                o.z = acc[a][b][i][2] + bias[2];
                o.w = acc[a][b][i][3] + bias[3];
                *reinterpret_cast<float4*>(&g_xg[(size_t)t * R4 + rbase]) = o;
            }
        }
    }
}

// fast sigmoid/tanh via HW EX2 path
__device__ __forceinline__ float sigmoidf_(float v) { return 1.0f / (1.0f + __expf(-v)); }
__device__ __forceinline__ float tanhf_(float v)    { return 2.0f / (1.0f + __expf(-2.0f * v)) - 1.0f; }
__device__ __forceinline__ __half2 u2h_(unsigned u) { return *reinterpret_cast<__half2*>(&u); }

// ---------------- persistent LSTM recurrence (R8 structure) ----------------
// Each warp computes 3 SMEM-cached rows (local rows 3w..3w+2, gates i/f/g) +
// 1 register-resident o-gate row (local row 48+w).
// Warp 0 publishes h (coalesced 64B store) while other warps run ahead.
__global__ __launch_bounds__(NTHR, 1) void lstm_rec() {
    extern __shared__ float smem[];
    __half* wc    = reinterpret_cast<__half*>(smem);         // NCACHE * HID halfs
    __half* h2_sh = wc + NCACHE * HID;                       // HID halfs
    float*  g_sh  = reinterpret_cast<float*>(h2_sh + HID);   // 64 gate pre-activations
    float*  c_sh  = g_sh + 64;                               // 16 cell states

    const int tid   = threadIdx.x;
    const int bid   = blockIdx.x;
    const int hbase = bid * HPB;

    // stage local rows 0..47 (gates i,f,g) into SMEM as fp16 (once)
    for (int idx = tid; idx < NCACHE * HID / 8; idx += NTHR) {
        const int lr  = idx >> 8;
        const int col = (idx & 255) * 8;
        const int gate = lr >> 4;
        const int hl   = lr & 15;
        const size_t row = (size_t)(gate * HID + hbase + hl);
        reinterpret_cast<uint4*>(wc + (size_t)lr * HID)[col / 8] =
            __ldg(reinterpret_cast<const uint4*>(g_whh + row * HID + col));
    }
    if (tid < HPB) c_sh[tid] = 0.0f;

    const int warp = tid >> 5;
    const int lane = tid & 31;

    // this warp's smem rows (gates i, f, g; local rows 3w..3w+2)
    const __half* ws0 = wc + (size_t)(3 * warp + 0) * HID;
    const __half* ws1 = wc + (size_t)(3 * warp + 1) * HID;
    const __half* ws2 = wc + (size_t)(3 * warp + 2) * HID;

    // o-gate row (local row 48+w): register-resident (8 x uint4 = 32 regs)
    uint4 wreg[8];
    {
        const __half* wo = g_whh + (size_t)(3 * HID + hbase + warp) * HID;
        #pragma unroll
        for (int ch = 0; ch < 8; ch++)
            wreg[ch] = __ldg(reinterpret_cast<const uint4*>(wo + ch * 256 + lane * 8));
    }

    // xg index for this lane's assigned local row (lanes 0..3)
    int my_lrow = (lane < 3) ? (3 * warp + lane) : (48 + warp);
    const size_t my_xg_row = (size_t)((my_lrow >> 4) * HID + hbase + (my_lrow & 15));

    // message staging: thread stages 4 floats of line (tid>>2)
    const int mb = tid >> 2;
    const int mq = tid & 3;

    for (int t = 0; t < TLEN; t++) {
        // xg prefetch (h-independent, overlaps the wait)
        float xgl = 0.f;
        if (lane < 4)
            xgl = __ldg(g_xg + (size_t)t * R4 + my_xg_row);

        // poll-and-stage: acquire-load tag, then pull h quarter
        {
            const Msg* ml = &g_msg[t & 1][mb];
            while (ld_acq_(&ml->tag) < (unsigned)t) { }
            float4 v = __ldcg(reinterpret_cast<const float4*>(ml->h + mq * 4));
            __half2 p0 = __floats2half2_rn(v.x, v.y);
            __half2 p1 = __floats2half2_rn(v.z, v.w);
            uint2 u;
            u.x = *reinterpret_cast<unsigned*>(&p0);
            u.y = *reinterpret_cast<unsigned*>(&p1);
            reinterpret_cast<uint2*>(h2_sh)[tid] = u;
        }
        __syncthreads();                                    // h2_sh complete

        // 3 smem rows + 1 reg row dot, HFMA2 chunks -> f32x2 accumulators
        ull acc0 = 0ull, acc1 = 0ull, acc2 = 0ull, acc3 = 0ull;
        #pragma unroll
        for (int ch = 0; ch < 8; ch++) {
            const int off = ch * 256 + lane * 8;   // half index
            uint4 hv = *reinterpret_cast<const uint4*>(h2_sh + off);
            uint4 w0 = *reinterpret_cast<const uint4*>(ws0 + off);
            uint4 w1 = *reinterpret_cast<const uint4*>(ws1 + off);
            uint4 w2 = *reinterpret_cast<const uint4*>(ws2 + off);
            uint4 w3 = wreg[ch];

            __half2 s0 = __hmul2(u2h_(w0.x), u2h_(hv.x));
            s0 = __hfma2(u2h_(w0.y), u2h_(hv.y), s0);
            s0 = __hfma2(u2h_(w0.z), u2h_(hv.z), s0);
            s0 = __hfma2(u2h_(w0.w), u2h_(hv.w), s0);
            __half2 s1 = __hmul2(u2h_(w1.x), u2h_(hv.x));
            s1 = __hfma2(u2h_(w1.y), u2h_(hv.y), s1);
            s1 = __hfma2(u2h_(w1.z), u2h_(hv.z), s1);
            s1 = __hfma2(u2h_(w1.w), u2h_(hv.w), s1);
            __half2 s2 = __hmul2(u2h_(w2.x), u2h_(hv.x));
            s2 = __hfma2(u2h_(w2.y), u2h_(hv.y), s2);
            s2 = __hfma2(u2h_(w2.z), u2h_(hv.z), s2);
            s2 = __hfma2(u2h_(w2.w), u2h_(hv.w), s2);
            __half2 s3 = __hmul2(u2h_(w3.x), u2h_(hv.x));
            s3 = __hfma2(u2h_(w3.y), u2h_(hv.y), s3);
            s3 = __hfma2(u2h_(w3.z), u2h_(hv.z), s3);
            s3 = __hfma2(u2h_(w3.w), u2h_(hv.w), s3);

            float2 f0 = __half22float2(s0);
            float2 f1 = __half22float2(s1);
            float2 f2 = __half22float2(s2);
            float2 f3 = __half22float2(s3);
            ull ff;
            asm("mov.b64 %0, {%1, %2};" : "=l"(ff) : "f"(f0.x), "f"(f0.y));
            asm("add.rn.f32x2 %0, %0, %1;" : "+l"(acc0) : "l"(ff));
            asm("mov.b64 %0, {%1, %2};" : "=l"(ff) : "f"(f1.x), "f"(f1.y));
            asm("add.rn.f32x2 %0, %0, %1;" : "+l"(acc1) : "l"(ff));
            asm("mov.b64 %0, {%1, %2};" : "=l"(ff) : "f"(f2.x), "f"(f2.y));
            asm("add.rn.f32x2 %0, %0, %1;" : "+l"(acc2) : "l"(ff));
            asm("mov.b64 %0, {%1, %2};" : "=l"(ff) : "f"(f3.x), "f"(f3.y));
            asm("add.rn.f32x2 %0, %0, %1;" : "+l"(acc3) : "l"(ff));
        }

        float a0, a1, a2, a3;
        {
            float lo, hi;
            asm("mov.b64 {%0, %1}, %2;" : "=f"(lo), "=f"(hi) : "l"(acc0)); a0 = lo + hi;
            asm("mov.b64 {%0, %1}, %2;" : "=f"(lo), "=f"(hi) : "l"(acc1)); a1 = lo + hi;
            asm("mov.b64 {%0, %1}, %2;" : "=f"(lo), "=f"(hi) : "l"(acc2)); a2 = lo + hi;
            asm("mov.b64 {%0, %1}, %2;" : "=f"(lo), "=f"(hi) : "l"(acc3)); a3 = lo + hi;
        }
        #pragma unroll
        for (int off = 16; off; off >>= 1) {
            a0 += __shfl_xor_sync(0xFFFFFFFFu, a0, off);
            a1 += __shfl_xor_sync(0xFFFFFFFFu, a1, off);
            a2 += __shfl_xor_sync(0xFFFFFFFFu, a2, off);
            a3 += __shfl_xor_sync(0xFFFFFFFFu, a3, off);
        }
        // bring lane-held xg values to lane 0 and write gate pre-activations
        const float x0 = __shfl_sync(0xFFFFFFFFu, xgl, 0);
        const float x1 = __shfl_sync(0xFFFFFFFFu, xgl, 1);
        const float x2 = __shfl_sync(0xFFFFFFFFu, xgl, 2);
        const float x3 = __shfl_sync(0xFFFFFFFFu, xgl, 3);
        if (lane == 0) {
            g_sh[3 * warp + 0] = a0 + x0;
            g_sh[3 * warp + 1] = a1 + x1;
            g_sh[3 * warp + 2] = a2 + x2;
            g_sh[48 + warp]    = a3 + x3;
        }
        __syncthreads();                                    // g_sh complete

        // warp 0: activations + publish (coalesced); other warps run ahead to next poll
        if (warp == 0) {
            if (tid < HPB) {
                const float iv = sigmoidf_(g_sh[tid]);
                const float fv = sigmoidf_(g_sh[16 + tid]);
                const float gv = tanhf_(g_sh[32 + tid]);
                const float ov = sigmoidf_(g_sh[48 + tid]);
                const float c  = fv * c_sh[tid] + iv * gv;
                c_sh[tid] = c;
                g_msg[(t + 1) & 1][bid].h[tid] = ov * tanhf_(c);
            }
            __syncwarp();
            if (lane == 0)
                st_rel_(&g_msg[(t + 1) & 1][bid].tag, (unsigned)(t + 1));
        }
    }
}

// ---------------- output layer ----------------
__global__ void out_kernel(const float* __restrict__ W_out,
                           const float* __restrict__ b_out,
                           float* __restrict__ out) {
    __shared__ float red[8];
    const int tid = threadIdx.x;   // 256 threads
    float s = 0.f;
    for (int j = tid; j < HID; j += 256) {
        float hv = g_msg[0][j >> 4].h[j & 15];   // final h (TLEN even -> buffer 0)
        s += hv * W_out[j];
    }
    #pragma unroll
    for (int off = 16; off; off >>= 1) s += __shfl_xor_sync(0xFFFFFFFFu, s, off);
    if ((tid & 31) == 0) red[tid >> 5] = s;
    __syncthreads();
    if (tid < 8) {
        float v = red[tid];
        #pragma unroll
        for (int off = 4; off; off >>= 1) v += __shfl_xor_sync(0xFFu, v, off);
        if (tid == 0) out[0] = v + b_out[0];
    }
}

// ---------------- launch ----------------
extern "C" void kernel_launch(void* const* d_in, const int* in_sizes, int n_in,
                              void* d_out, int out_size) {
    const float* x     = (const float*)d_in[0];
    const float* W_ih  = (const float*)d_in[1];
    const float* W_hh  = (const float*)d_in[2];
    const float* b_ih  = (const float*)d_in[3];
    const float* b_hh  = (const float*)d_in[4];
    const float* W_out = (const float*)d_in[5];
    const float* b_out = (const float*)d_in[6];
    float* out = (float*)d_out;

    init_kernel<<<1, 256>>>();
    prep_whh<<<2048, 256>>>(W_hh);

    dim3 ggrid(R4 / GBN, TLEN / GBM);
    xg_gemm<<<ggrid, 256>>>(x, W_ih, b_ih, b_hh);

    cudaFuncSetAttribute(lstm_rec, cudaFuncAttributeMaxDynamicSharedMemorySize, REC_SMEM_BYTES);
    lstm_rec<<<NBLK, NTHR, REC_SMEM_BYTES>>>();

    out_kernel<<<1, 256>>>(W_out, b_out, out);
}

// round 15
// speedup vs baseline: 1.7674x; 1.2519x over previous
#include <cuda_runtime.h>
#include <cuda_fp16.h>
#include <math.h>
#include <stdint.h>

typedef unsigned long long ull;

// ---------------- problem constants ----------------
#define HID  2048
#define R4   8192          // 4 * HID
#define TLEN 4096
#define IDIM 1024

// ---------------- recurrence kernel config ----------------
#define NBLK   128
#define NTHR   512
#define HPB    16          // h indices per block (2048 / 128)
#define NCACHE 48          // rows of W_hh (fp16) cached in SMEM per block (gates i,f,g)

// smem: 48 rows * 2048 halfs + h 2048 halfs + g 64 f + c 16 f
#define REC_SMEM_BYTES (NCACHE * HID * 2 + HID * 2 + (64 + 16) * 4)

// ---------------- scratch (device globals; no allocation) ----------------
__device__ float    g_xg[(size_t)TLEN * R4];      // precomputed input gates, 128 MB
__device__ __half   g_whh[(size_t)R4 * HID];      // fp16 copy of W_hh, 32 MB
__device__ float    g_hfinal[HID];                // fp32 final hidden state

// self-validating 8B message word: low 32b = 2 fp16 h values, high 32b = tag.
// 8B aligned relaxed atomics are single-copy atomic -> no tearing, no fences.
// 8 words per block (16 h values), padded to a 128B line; double buffered.
struct alignas(128) Msg8 { ull w[8]; ull pad[8]; };
__device__ Msg8 g_msg[2][NBLK];

// ---------------- relaxed 64-bit atomics ----------------
__device__ __forceinline__ ull ld64_(const ull* p) {
    ull v;
    asm volatile("ld.relaxed.gpu.global.b64 %0, [%1];" : "=l"(v) : "l"(p) : "memory");
    return v;
}
__device__ __forceinline__ void st64_(ull* p, ull v) {
    asm volatile("st.relaxed.gpu.global.b64 [%0], %1;" :: "l"(p), "l"(v) : "memory");
}

// ---------------- init ----------------
__global__ void init_kernel() {
    unsigned* p = reinterpret_cast<unsigned*>(g_msg);
    for (int i = threadIdx.x; i < 2 * NBLK * 32; i += blockDim.x) p[i] = 0u;
}

// ---------------- W_hh fp32 -> fp16 ----------------
__global__ void prep_whh(const float* __restrict__ W_hh) {
    const size_t n2 = (size_t)R4 * HID / 2;
    const size_t stride = (size_t)gridDim.x * blockDim.x;
    for (size_t i = (size_t)blockIdx.x * blockDim.x + threadIdx.x; i < n2; i += stride) {
        float2 v = reinterpret_cast<const float2*>(W_hh)[i];
        reinterpret_cast<__half2*>(g_whh)[i] = __floats2half2_rn(v.x, v.y);
    }
}

// ---------------- xg GEMM: 128x128x16 tiles, 8x8 micro (proven) ----------------
#define GBM 128
#define GBN 128
#define GBK 16
#define GAP 132

__global__ __launch_bounds__(256) void xg_gemm(const float* __restrict__ x,
                                               const float* __restrict__ W_ih,
                                               const float* __restrict__ b_ih,
                                               const float* __restrict__ b_hh) {
    __shared__ float As[GBK * GAP];
    __shared__ float Bs[GBK * GAP];
    const int tid = threadIdx.x;
    const int tx = tid & 15;
    const int ty = tid >> 4;
    const int rt = blockIdx.x * GBN;
    const int tt = blockIdx.y * GBM;

    const int lr = tid >> 2;
    const int lc = (tid & 3) * 4;

    float acc[2][2][4][4];
    #pragma unroll
    for (int a = 0; a < 2; a++)
        #pragma unroll
        for (int b = 0; b < 2; b++)
            #pragma unroll
            for (int i = 0; i < 4; i++)
                #pragma unroll
                for (int j = 0; j < 4; j++) acc[a][b][i][j] = 0.f;

    for (int k0 = 0; k0 < IDIM; k0 += GBK) {
        float4 a0 = __ldg(reinterpret_cast<const float4*>(&x[(size_t)(tt + lr) * IDIM + k0 + lc]));
        float4 a1 = __ldg(reinterpret_cast<const float4*>(&x[(size_t)(tt + lr + 64) * IDIM + k0 + lc]));
        float4 w0 = __ldg(reinterpret_cast<const float4*>(&W_ih[(size_t)(rt + lr) * IDIM + k0 + lc]));
        float4 w1 = __ldg(reinterpret_cast<const float4*>(&W_ih[(size_t)(rt + lr + 64) * IDIM + k0 + lc]));

        As[(lc + 0) * GAP + lr] = a0.x; As[(lc + 1) * GAP + lr] = a0.y;
        As[(lc + 2) * GAP + lr] = a0.z; As[(lc + 3) * GAP + lr] = a0.w;
        As[(lc + 0) * GAP + lr + 64] = a1.x; As[(lc + 1) * GAP + lr + 64] = a1.y;
        As[(lc + 2) * GAP + lr + 64] = a1.z; As[(lc + 3) * GAP + lr + 64] = a1.w;

        Bs[(lc + 0) * GAP + lr] = w0.x; Bs[(lc + 1) * GAP + lr] = w0.y;
        Bs[(lc + 2) * GAP + lr] = w0.z; Bs[(lc + 3) * GAP + lr] = w0.w;
        Bs[(lc + 0) * GAP + lr + 64] = w1.x; Bs[(lc + 1) * GAP + lr + 64] = w1.y;
        Bs[(lc + 2) * GAP + lr + 64] = w1.z; Bs[(lc + 3) * GAP + lr + 64] = w1.w;

        __syncthreads();

        #pragma unroll
        for (int k = 0; k < GBK; k++) {
            float4 av0 = *reinterpret_cast<const float4*>(&As[k * GAP + ty * 4]);
            float4 av1 = *reinterpret_cast<const float4*>(&As[k * GAP + 64 + ty * 4]);
            float4 bv0 = *reinterpret_cast<const float4*>(&Bs[k * GAP + tx * 4]);
            float4 bv1 = *reinterpret_cast<const float4*>(&Bs[k * GAP + 64 + tx * 4]);
            float am[2][4] = {{av0.x, av0.y, av0.z, av0.w}, {av1.x, av1.y, av1.z, av1.w}};
            float bn[2][4] = {{bv0.x, bv0.y, bv0.z, bv0.w}, {bv1.x, bv1.y, bv1.z, bv1.w}};
            #pragma unroll
            for (int a = 0; a < 2; a++)
                #pragma unroll
                for (int i = 0; i < 4; i++)
                    #pragma unroll
                    for (int b = 0; b < 2; b++)
                        #pragma unroll
                        for (int j = 0; j < 4; j++)
                            acc[a][b][i][j] += am[a][i] * bn[b][j];
        }
        __syncthreads();
    }

    #pragma unroll
    for (int b = 0; b < 2; b++) {
        const int rbase = rt + b * 64 + tx * 4;
        float bias[4];
        #pragma unroll
        for (int j = 0; j < 4; j++) bias[j] = b_ih[rbase + j] + b_hh[rbase + j];
        #pragma unroll
        for (int a = 0; a < 2; a++) {
            #pragma unroll
            for (int i = 0; i < 4; i++) {
                const int t = tt + a * 64 + ty * 4 + i;
                float4 o;
                o.x = acc[a][b][i][0] + bias[0];
                o.y = acc[a][b][i][1] + bias[1];
                o.z = acc[a][b][i][2] + bias[2];
                o.w = acc[a][b][i][3] + bias[3];
                *reinterpret_cast<float4*>(&g_xg[(size_t)t * R4 + rbase]) = o;
            }
        }
    }
}

// fast sigmoid/tanh via HW EX2 path
__device__ __forceinline__ float sigmoidf_(float v) { return 1.0f / (1.0f + __expf(-v)); }
__device__ __forceinline__ float tanhf_(float v)    { return 2.0f / (1.0f + __expf(-2.0f * v)) - 1.0f; }
__device__ __forceinline__ __half2 u2h_(unsigned u) { return *reinterpret_cast<__half2*>(&u); }

// ---------------- persistent LSTM recurrence ----------------
// Each warp computes 3 SMEM-cached rows (local rows 3w..3w+2, gates i/f/g) +
// 1 register-resident o-gate row (local row 48+w).
// Warp 0 publishes h as 8 self-validating 8B words; other warps run ahead.
__global__ __launch_bounds__(NTHR, 1) void lstm_rec() {
    extern __shared__ float smem[];
    __half* wc    = reinterpret_cast<__half*>(smem);         // NCACHE * HID halfs
    __half* h2_sh = wc + NCACHE * HID;                       // HID halfs
    float*  g_sh  = reinterpret_cast<float*>(h2_sh + HID);   // 64 gate pre-activations
    float*  c_sh  = g_sh + 64;                               // 16 cell states

    const int tid   = threadIdx.x;
    const int bid   = blockIdx.x;
    const int hbase = bid * HPB;

    // stage local rows 0..47 (gates i,f,g) into SMEM as fp16 (once)
    for (int idx = tid; idx < NCACHE * HID / 8; idx += NTHR) {
        const int lr  = idx >> 8;
        const int col = (idx & 255) * 8;
        const int gate = lr >> 4;
        const int hl   = lr & 15;
        const size_t row = (size_t)(gate * HID + hbase + hl);
        reinterpret_cast<uint4*>(wc + (size_t)lr * HID)[col / 8] =
            __ldg(reinterpret_cast<const uint4*>(g_whh + row * HID + col));
    }
    if (tid < HPB) c_sh[tid] = 0.0f;

    const int warp = tid >> 5;
    const int lane = tid & 31;

    // this warp's smem rows (gates i, f, g; local rows 3w..3w+2)
    const __half* ws0 = wc + (size_t)(3 * warp + 0) * HID;
    const __half* ws1 = wc + (size_t)(3 * warp + 1) * HID;
    const __half* ws2 = wc + (size_t)(3 * warp + 2) * HID;

    // o-gate row (local row 48+w): register-resident (8 x uint4 = 32 regs)
    uint4 wreg[8];
    {
        const __half* wo = g_whh + (size_t)(3 * HID + hbase + warp) * HID;
        #pragma unroll
        for (int ch = 0; ch < 8; ch++)
            wreg[ch] = __ldg(reinterpret_cast<const uint4*>(wo + ch * 256 + lane * 8));
    }

    // xg index for this lane's assigned local row (lanes 0..3)
    int my_lrow = (lane < 3) ? (3 * warp + lane) : (48 + warp);
    const size_t my_xg_row = (size_t)((my_lrow >> 4) * HID + hbase + (my_lrow & 15));

    // message staging: thread polls words 2*(tid&3), 2*(tid&3)+1 of block (tid>>2)
    const int mb = tid >> 2;
    const int mq = tid & 3;

    for (int t = 0; t < TLEN; t++) {
        // xg prefetch (h-independent, overlaps the wait)
        float xgl = 0.f;
        if (lane < 4)
            xgl = __ldg(g_xg + (size_t)t * R4 + my_xg_row);

        // one-hop poll: two 8B words (each = 2 fp16 h + tag), both loads in flight
        {
            const ull* wp = &g_msg[t & 1][mb].w[2 * mq];
            ull a = ld64_(wp);
            ull b = ld64_(wp + 1);
            while ((unsigned)(a >> 32) < (unsigned)t || (unsigned)(b >> 32) < (unsigned)t) {
                a = ld64_(wp);
                b = ld64_(wp + 1);
            }
            reinterpret_cast<uint2*>(h2_sh)[tid] = make_uint2((unsigned)a, (unsigned)b);
        }
        __syncthreads();                                    // h2_sh complete

        // dot: paired chunks (16-product fp16 chains) -> f32x2 accumulators
        ull acc0 = 0ull, acc1 = 0ull, acc2 = 0ull, acc3 = 0ull;
        #pragma unroll
        for (int cp = 0; cp < 4; cp++) {
            const int offA = cp * 512 + lane * 8;   // half index
            const int offB = offA + 256;
            uint4 hvA = *reinterpret_cast<const uint4*>(h2_sh + offA);
            uint4 hvB = *reinterpret_cast<const uint4*>(h2_sh + offB);
            uint4 w0A = *reinterpret_cast<const uint4*>(ws0 + offA);
            uint4 w0B = *reinterpret_cast<const uint4*>(ws0 + offB);
            uint4 w1A = *reinterpret_cast<const uint4*>(ws1 + offA);
            uint4 w1B = *reinterpret_cast<const uint4*>(ws1 + offB);
            uint4 w2A = *reinterpret_cast<const uint4*>(ws2 + offA);
            uint4 w2B = *reinterpret_cast<const uint4*>(ws2 + offB);
            uint4 w3A = wreg[2 * cp];
            uint4 w3B = wreg[2 * cp + 1];

            __half2 s0 = __hmul2(u2h_(w0A.x), u2h_(hvA.x));
            s0 = __hfma2(u2h_(w0A.y), u2h_(hvA.y), s0);
            s0 = __hfma2(u2h_(w0A.z), u2h_(hvA.z), s0);
            s0 = __hfma2(u2h_(w0A.w), u2h_(hvA.w), s0);
            s0 = __hfma2(u2h_(w0B.x), u2h_(hvB.x), s0);
            s0 = __hfma2(u2h_(w0B.y), u2h_(hvB.y), s0);
            s0 = __hfma2(u2h_(w0B.z), u2h_(hvB.z), s0);
            s0 = __hfma2(u2h_(w0B.w), u2h_(hvB.w), s0);

            __half2 s1 = __hmul2(u2h_(w1A.x), u2h_(hvA.x));
            s1 = __hfma2(u2h_(w1A.y), u2h_(hvA.y), s1);
            s1 = __hfma2(u2h_(w1A.z), u2h_(hvA.z), s1);
            s1 = __hfma2(u2h_(w1A.w), u2h_(hvA.w), s1);
            s1 = __hfma2(u2h_(w1B.x), u2h_(hvB.x), s1);
            s1 = __hfma2(u2h_(w1B.y), u2h_(hvB.y), s1);
            s1 = __hfma2(u2h_(w1B.z), u2h_(hvB.z), s1);
            s1 = __hfma2(u2h_(w1B.w), u2h_(hvB.w), s1);

            __half2 s2 = __hmul2(u2h_(w2A.x), u2h_(hvA.x));
            s2 = __hfma2(u2h_(w2A.y), u2h_(hvA.y), s2);
            s2 = __hfma2(u2h_(w2A.z), u2h_(hvA.z), s2);
            s2 = __hfma2(u2h_(w2A.w), u2h_(hvA.w), s2);
            s2 = __hfma2(u2h_(w2B.x), u2h_(hvB.x), s2);
            s2 = __hfma2(u2h_(w2B.y), u2h_(hvB.y), s2);
            s2 = __hfma2(u2h_(w2B.z), u2h_(hvB.z), s2);
            s2 = __hfma2(u2h_(w2B.w), u2h_(hvB.w), s2);

            __half2 s3 = __hmul2(u2h_(w3A.x), u2h_(hvA.x));
            s3 = __hfma2(u2h_(w3A.y), u2h_(hvA.y), s3);
            s3 = __hfma2(u2h_(w3A.z), u2h_(hvA.z), s3);
            s3 = __hfma2(u2h_(w3A.w), u2h_(hvA.w), s3);
            s3 = __hfma2(u2h_(w3B.x), u2h_(hvB.x), s3);
            s3 = __hfma2(u2h_(w3B.y), u2h_(hvB.y), s3);
            s3 = __hfma2(u2h_(w3B.z), u2h_(hvB.z), s3);
            s3 = __hfma2(u2h_(w3B.w), u2h_(hvB.w), s3);

            float2 f0 = __half22float2(s0);
            float2 f1 = __half22float2(s1);
            float2 f2 = __half22float2(s2);
            float2 f3 = __half22float2(s3);
            ull ff;
            asm("mov.b64 %0, {%1, %2};" : "=l"(ff) : "f"(f0.x), "f"(f0.y));
            asm("add.rn.f32x2 %0, %0, %1;" : "+l"(acc0) : "l"(ff));
            asm("mov.b64 %0, {%1, %2};" : "=l"(ff) : "f"(f1.x), "f"(f1.y));
            asm("add.rn.f32x2 %0, %0, %1;" : "+l"(acc1) : "l"(ff));
            asm("mov.b64 %0, {%1, %2};" : "=l"(ff) : "f"(f2.x), "f"(f2.y));
            asm("add.rn.f32x2 %0, %0, %1;" : "+l"(acc2) : "l"(ff));
            asm("mov.b64 %0, {%1, %2};" : "=l"(ff) : "f"(f3.x), "f"(f3.y));
            asm("add.rn.f32x2 %0, %0, %1;" : "+l"(acc3) : "l"(ff));
        }

        float a0, a1, a2, a3;
        {
            float lo, hi;
            asm("mov.b64 {%0, %1}, %2;" : "=f"(lo), "=f"(hi) : "l"(acc0)); a0 = lo + hi;
            asm("mov.b64 {%0, %1}, %2;" : "=f"(lo), "=f"(hi) : "l"(acc1)); a1 = lo + hi;
            asm("mov.b64 {%0, %1}, %2;" : "=f"(lo), "=f"(hi) : "l"(acc2)); a2 = lo + hi;
            asm("mov.b64 {%0, %1}, %2;" : "=f"(lo), "=f"(hi) : "l"(acc3)); a3 = lo + hi;
        }
        #pragma unroll
        for (int off = 16; off; off >>= 1) {
            a0 += __shfl_xor_sync(0xFFFFFFFFu, a0, off);
            a1 += __shfl_xor_sync(0xFFFFFFFFu, a1, off);
            a2 += __shfl_xor_sync(0xFFFFFFFFu, a2, off);
            a3 += __shfl_xor_sync(0xFFFFFFFFu, a3, off);
        }
        // bring lane-held xg values to lane 0 and write gate pre-activations
        const float x0 = __shfl_sync(0xFFFFFFFFu, xgl, 0);
        const float x1 = __shfl_sync(0xFFFFFFFFu, xgl, 1);
        const float x2 = __shfl_sync(0xFFFFFFFFu, xgl, 2);
        const float x3 = __shfl_sync(0xFFFFFFFFu, xgl, 3);
        if (lane == 0) {
            g_sh[3 * warp + 0] = a0 + x0;
            g_sh[3 * warp + 1] = a1 + x1;
            g_sh[3 * warp + 2] = a2 + x2;
            g_sh[48 + warp]    = a3 + x3;
        }
        __syncthreads();                                    // g_sh complete

        // warp 0: activations + publish; other warps run ahead to next poll
        if (warp == 0) {
            float hval = 0.f;
            if (lane < HPB) {
                const float iv = sigmoidf_(g_sh[lane]);
                const float fv = sigmoidf_(g_sh[16 + lane]);
                const float gv = tanhf_(g_sh[32 + lane]);
                const float ov = sigmoidf_(g_sh[48 + lane]);
                const float c  = fv * c_sh[lane] + iv * gv;
                c_sh[lane] = c;
                hval = ov * tanhf_(c);
                if (t == TLEN - 1) g_hfinal[hbase + lane] = hval;
            }
            // gather 2 h values per word to lanes 0..7; publish 8B words (data+tag)
            const float v0 = __shfl_sync(0xFFFFFFFFu, hval, (lane * 2 + 0) & 31);
            const float v1 = __shfl_sync(0xFFFFFFFFu, hval, (lane * 2 + 1) & 31);
            if (lane < 8) {
                __half2 hp = __floats2half2_rn(v0, v1);
                ull w = (ull)(*reinterpret_cast<unsigned*>(&hp))
                      | ((ull)(unsigned)(t + 1) << 32);
                st64_(&g_msg[(t + 1) & 1][bid].w[lane], w);
            }
        }
    }
}

// ---------------- output layer ----------------
__global__ void out_kernel(const float* __restrict__ W_out,
                           const float* __restrict__ b_out,
                           float* __restrict__ out) {
    __shared__ float red[8];
    const int tid = threadIdx.x;   // 256 threads
    float s = 0.f;
    for (int j = tid; j < HID; j += 256) s += g_hfinal[j] * W_out[j];
    #pragma unroll
    for (int off = 16; off; off >>= 1) s += __shfl_xor_sync(0xFFFFFFFFu, s, off);
    if ((tid & 31) == 0) red[tid >> 5] = s;
    __syncthreads();
    if (tid < 8) {
        float v = red[tid];
        #pragma unroll
        for (int off = 4; off; off >>= 1) v += __shfl_xor_sync(0xFFu, v, off);
        if (tid == 0) out[0] = v + b_out[0];
    }
}

// ---------------- launch ----------------
extern "C" void kernel_launch(void* const* d_in, const int* in_sizes, int n_in,
                              void* d_out, int out_size) {
    const float* x     = (const float*)d_in[0];
    const float* W_ih  = (const float*)d_in[1];
    const float* W_hh  = (const float*)d_in[2];
    const float* b_ih  = (const float*)d_in[3];
    const float* b_hh  = (const float*)d_in[4];
    const float* W_out = (const float*)d_in[5];
    const float* b_out = (const float*)d_in[6];
    float* out = (float*)d_out;

    init_kernel<<<1, 256>>>();
    prep_whh<<<2048, 256>>>(W_hh);

    dim3 ggrid(R4 / GBN, TLEN / GBM);
    xg_gemm<<<ggrid, 256>>>(x, W_ih, b_ih, b_hh);

    cudaFuncSetAttribute(lstm_rec, cudaFuncAttributeMaxDynamicSharedMemorySize, REC_SMEM_BYTES);
    lstm_rec<<<NBLK, NTHR, REC_SMEM_BYTES>>>();

    out_kernel<<<1, 256>>>(W_out, b_out, out);
}